// round 5
// baseline (speedup 1.0000x reference)
#include <cuda_runtime.h>
#include <math.h>

// ---------------------------------------------------------------------------
// GIN (3 GINConv layers + BN + ReLU + MLP head)
//   N_NODES=100000, N_EDGES=1200000, D_IN=128, D_H=64, N_GRAPHS=256
// R4 changes vs R3:
//   * MLP kernels: 2 threads per node (32 cols each), warp-pair shuffle
//     exchange of the k-vector -> regs ~158->~95, warps/SM ~21->~42
//   * pull64: 8-way unrolled neighbor loop
// ---------------------------------------------------------------------------

#define MAX_NODES 100000
#define MAX_EDGES 1200000
#define NGRAPH    256
#define SCAN_B    1024
#define MAX_SCAN_BLOCKS 128

__device__ float g_buf [MAX_NODES * 128];     // y | z
__device__ float g_h1  [MAX_NODES * 64];
__device__ float g_h2  [MAX_NODES * 64];
__device__ float g_h3  [MAX_NODES * 64];
__device__ float g_pool[NGRAPH * 192];
__device__ int   g_deg [MAX_NODES + 1];
__device__ int   g_row [MAX_NODES + 1];
__device__ int   g_cur [MAX_NODES];
__device__ int   g_col [MAX_EDGES];
__device__ int   g_bsum[MAX_SCAN_BLOCKS];

typedef unsigned long long ull;

__device__ __forceinline__ ull pack2(float lo, float hi) {
    ull r; asm("mov.b64 %0,{%1,%2};" : "=l"(r) : "f"(lo), "f"(hi)); return r;
}
__device__ __forceinline__ void unpack2(ull v, float& lo, float& hi) {
    asm("mov.b64 {%0,%1},%2;" : "=f"(lo), "=f"(hi) : "l"(v));
}
__device__ __forceinline__ ull fma2(ull a, ull b, ull c) {
    ull d; asm("fma.rn.f32x2 %0,%1,%2,%3;" : "=l"(d) : "l"(a), "l"(b), "l"(c)); return d;
}

// One k-step against 32 output columns (16 ull accumulators).
__device__ __forceinline__ void fma_k32(ull* acc2, const float* ws, int k,
                                        int halfoff, float v) {
    ull hk2 = pack2(v, v);
    const ulonglong2* wrow = (const ulonglong2*)(ws + k * 64 + halfoff);
#pragma unroll
    for (int j8 = 0; j8 < 8; j8++) {
        ulonglong2 wv = wrow[j8];
        acc2[j8 * 2 + 0] = fma2(hk2, wv.x, acc2[j8 * 2 + 0]);
        acc2[j8 * 2 + 1] = fma2(hk2, wv.y, acc2[j8 * 2 + 1]);
    }
}

// ---------------------------------------------------------------------------
__global__ void zero_f_kernel(float* __restrict__ p, int n) {
    int i = blockIdx.x * blockDim.x + threadIdx.x;
    if (i < n) p[i] = 0.f;
}
__global__ void zero_i_kernel(int* __restrict__ p, int n) {
    int i = blockIdx.x * blockDim.x + threadIdx.x;
    if (i < n) p[i] = 0;
}

// ---------------------------------------------------------------------------
// CSR build
// ---------------------------------------------------------------------------
__global__ void hist_kernel(const int* __restrict__ ei, int* __restrict__ deg, int n_edges) {
    int e = blockIdx.x * blockDim.x + threadIdx.x;
    if (e < n_edges) atomicAdd(deg + __ldg(ei + n_edges + e), 1);
}

__global__ void bsum_kernel(const int* __restrict__ deg, int* __restrict__ bsum, int n) {
    __shared__ int sm[SCAN_B];
    int i = blockIdx.x * SCAN_B + threadIdx.x;
    sm[threadIdx.x] = (i < n) ? deg[i] : 0;
    __syncthreads();
#pragma unroll
    for (int off = SCAN_B / 2; off > 0; off >>= 1) {
        if (threadIdx.x < off) sm[threadIdx.x] += sm[threadIdx.x + off];
        __syncthreads();
    }
    if (threadIdx.x == 0) bsum[blockIdx.x] = sm[0];
}

__global__ void bscan_kernel(int* __restrict__ bsum, int nb) {
    if (threadIdx.x == 0) {
        int run = 0;
        for (int i = 0; i < nb; i++) { int v = bsum[i]; bsum[i] = run; run += v; }
    }
}

__global__ void scatter_scan_kernel(const int* __restrict__ deg,
                                    const int* __restrict__ bsum,
                                    int* __restrict__ rowptr, int* __restrict__ cur, int n) {
    __shared__ int sm[SCAN_B];
    int i = blockIdx.x * SCAN_B + threadIdx.x;
    int v = (i < n) ? deg[i] : 0;
    sm[threadIdx.x] = v;
    __syncthreads();
#pragma unroll
    for (int off = 1; off < SCAN_B; off *= 2) {
        int t = (threadIdx.x >= off) ? sm[threadIdx.x - off] : 0;
        __syncthreads();
        sm[threadIdx.x] += t;
        __syncthreads();
    }
    int excl = sm[threadIdx.x] - v + bsum[blockIdx.x];
    if (i < n) { rowptr[i] = excl; cur[i] = excl; }
    if (i == n - 1) rowptr[n] = excl + v;
}

__global__ void fill_kernel(const int* __restrict__ ei, int* __restrict__ cur,
                            int* __restrict__ col, int n_edges) {
    int e = blockIdx.x * blockDim.x + threadIdx.x;
    if (e >= n_edges) return;
    int s = __ldg(ei + e);
    int d = __ldg(ei + n_edges + e);
    int pos = atomicAdd(cur + d, 1);
    col[pos] = s;
}

// ---------------------------------------------------------------------------
// Pull aggregation on 64-dim rows: out[i] = in[i] + sum_{j in nb(i)} in[j]
// 16 threads per node, 8-way unrolled neighbor loop.
// ---------------------------------------------------------------------------
__global__ void pull64_kernel(const float* __restrict__ hin,
                              const int* __restrict__ rowptr,
                              const int* __restrict__ col,
                              float* __restrict__ hout, int n_nodes) {
    int t = blockIdx.x * blockDim.x + threadIdx.x;
    int node = t >> 4, lane = t & 15;
    if (node >= n_nodes) return;
    const float4* base = (const float4*)hin;
    float4 acc = __ldg(base + (size_t)node * 16 + lane);
    int e   = __ldg(rowptr + node);
    int end = __ldg(rowptr + node + 1);
    for (; e + 8 <= end; e += 8) {
        int s0 = __ldg(col + e),     s1 = __ldg(col + e + 1);
        int s2 = __ldg(col + e + 2), s3 = __ldg(col + e + 3);
        int s4 = __ldg(col + e + 4), s5 = __ldg(col + e + 5);
        int s6 = __ldg(col + e + 6), s7 = __ldg(col + e + 7);
        float4 v0 = __ldg(base + (size_t)s0 * 16 + lane);
        float4 v1 = __ldg(base + (size_t)s1 * 16 + lane);
        float4 v2 = __ldg(base + (size_t)s2 * 16 + lane);
        float4 v3 = __ldg(base + (size_t)s3 * 16 + lane);
        float4 v4 = __ldg(base + (size_t)s4 * 16 + lane);
        float4 v5 = __ldg(base + (size_t)s5 * 16 + lane);
        float4 v6 = __ldg(base + (size_t)s6 * 16 + lane);
        float4 v7 = __ldg(base + (size_t)s7 * 16 + lane);
        acc.x += ((v0.x + v1.x) + (v2.x + v3.x)) + ((v4.x + v5.x) + (v6.x + v7.x));
        acc.y += ((v0.y + v1.y) + (v2.y + v3.y)) + ((v4.y + v5.y) + (v6.y + v7.y));
        acc.z += ((v0.z + v1.z) + (v2.z + v3.z)) + ((v4.z + v5.z) + (v6.z + v7.z));
        acc.w += ((v0.w + v1.w) + (v2.w + v3.w)) + ((v4.w + v5.w) + (v6.w + v7.w));
    }
    for (; e + 4 <= end; e += 4) {
        int s0 = __ldg(col + e),     s1 = __ldg(col + e + 1);
        int s2 = __ldg(col + e + 2), s3 = __ldg(col + e + 3);
        float4 v0 = __ldg(base + (size_t)s0 * 16 + lane);
        float4 v1 = __ldg(base + (size_t)s1 * 16 + lane);
        float4 v2 = __ldg(base + (size_t)s2 * 16 + lane);
        float4 v3 = __ldg(base + (size_t)s3 * 16 + lane);
        acc.x += (v0.x + v1.x) + (v2.x + v3.x);
        acc.y += (v0.y + v1.y) + (v2.y + v3.y);
        acc.z += (v0.z + v1.z) + (v2.z + v3.z);
        acc.w += (v0.w + v1.w) + (v2.w + v3.w);
    }
    for (; e < end; e++) {
        int s = __ldg(col + e);
        float4 v = __ldg(base + (size_t)s * 16 + lane);
        acc.x += v.x; acc.y += v.y; acc.z += v.z; acc.w += v.w;
    }
    ((float4*)hout)[(size_t)node * 16 + lane] = acc;
}

// ---------------------------------------------------------------------------
// gemmA: y = x @ w1  (x: [N,128]). 2 threads/node, 32 cols each; the pair
// exchanges k-vector halves via shfl.xor(1).
// ---------------------------------------------------------------------------
__global__ __launch_bounds__(256) void gemmA_kernel(
    const float* __restrict__ x, const float* __restrict__ w1,
    float* __restrict__ y, int n_nodes)
{
    __shared__ float ws[128 * 64];
    int tid = threadIdx.x;
    for (int i = tid; i < 128 * 64; i += 256) ws[i] = w1[i];
    __syncthreads();

    int t    = blockIdx.x * 256 + tid;
    int node = t >> 1, half = t & 1;
    bool active = node < n_nodes;
    int  nodec  = active ? node : (n_nodes - 1);
    int  halfoff = half * 32;

    // own half of the 128-dim input row: 64 floats
    float4 xv[16];
    const float4* arow = (const float4*)(x + (size_t)nodec * 128) + half * 16;
#pragma unroll
    for (int q = 0; q < 16; q++) xv[q] = __ldg(arow + q);
    const float* xf = (const float*)xv;

    ull acc2[16];
#pragma unroll
    for (int j = 0; j < 16; j++) acc2[j] = 0ull;

#pragma unroll
    for (int kk2 = 0; kk2 < 32; kk2++) {
        float a0 = xf[kk2 * 2], a1 = xf[kk2 * 2 + 1];
        float b0 = __shfl_xor_sync(0xffffffffu, a0, 1);
        float b1 = __shfl_xor_sync(0xffffffffu, a1, 1);
        int kown = half * 64 + kk2 * 2;
        int kpar = (half ^ 1) * 64 + kk2 * 2;
        fma_k32(acc2, ws, kown,     halfoff, a0);
        fma_k32(acc2, ws, kown + 1, halfoff, a1);
        fma_k32(acc2, ws, kpar,     halfoff, b0);
        fma_k32(acc2, ws, kpar + 1, halfoff, b1);
    }

    if (active) {
        float4* orow = (float4*)(y + (size_t)node * 64 + halfoff);
#pragma unroll
        for (int q = 0; q < 8; q++) {
            float a, b, c, d;
            unpack2(acc2[q * 2 + 0], a, b);
            unpack2(acc2[q * 2 + 1], c, d);
            orow[q] = make_float4(a, b, c, d);
        }
    }
}

// ---------------------------------------------------------------------------
// Shared epilogue: GEMM2 (h @ w2) with pair exchange + bias/relu/store/pool.
// hreg: 16 ull = own 32 h values (k = half*32 .. +32).
// ---------------------------------------------------------------------------
__device__ __forceinline__ void gemm2_epilogue(
    const float* ws, const ull* hreg, int half, int halfoff,
    const float* __restrict__ b2, float* orow_base, float* prow, bool active)
{
    ull out2[16];
#pragma unroll
    for (int j = 0; j < 16; j++) out2[j] = 0ull;

#pragma unroll
    for (int kk2 = 0; kk2 < 16; kk2++) {
        float a0, a1;
        unpack2(hreg[kk2], a0, a1);
        float b0 = __shfl_xor_sync(0xffffffffu, a0, 1);
        float b1 = __shfl_xor_sync(0xffffffffu, a1, 1);
        int kown = half * 32 + kk2 * 2;
        int kpar = (half ^ 1) * 32 + kk2 * 2;
        fma_k32(out2, ws, kown,     halfoff, a0);
        fma_k32(out2, ws, kown + 1, halfoff, a1);
        fma_k32(out2, ws, kpar,     halfoff, b0);
        fma_k32(out2, ws, kpar + 1, halfoff, b1);
    }

    if (active) {
        float4* orow = (float4*)(orow_base + halfoff);
#pragma unroll
        for (int q = 0; q < 8; q++) {
            int j = halfoff + q * 4;
            float a0, a1, a2, a3;
            unpack2(out2[q * 2 + 0], a0, a1);
            unpack2(out2[q * 2 + 1], a2, a3);
            float4 v;
            v.x = fmaxf(a0 + __ldg(b2 + j + 0), 0.f);
            v.y = fmaxf(a1 + __ldg(b2 + j + 1), 0.f);
            v.z = fmaxf(a2 + __ldg(b2 + j + 2), 0.f);
            v.w = fmaxf(a3 + __ldg(b2 + j + 3), 0.f);
            orow[q] = v;
            asm volatile("red.global.add.v4.f32 [%0], {%1,%2,%3,%4};"
                         :: "l"(prow + j), "f"(v.x), "f"(v.y), "f"(v.z), "f"(v.w)
                         : "memory");
        }
    }
}

// BN+ReLU for own 32 columns (packed pairs), j = halfoff + 2*j2.
__device__ __forceinline__ void bn_relu32(
    ull* vals, int halfoff,
    const float* __restrict__ b1, const float* __restrict__ gg,
    const float* __restrict__ bt, const float* __restrict__ rm,
    const float* __restrict__ rv)
{
#pragma unroll
    for (int j2 = 0; j2 < 16; j2++) {
        float a, b;
        unpack2(vals[j2], a, b);
        int j = halfoff + j2 * 2;
        float sc0 = __ldg(gg + j)     * rsqrtf(__ldg(rv + j)     + 1e-5f);
        float sc1 = __ldg(gg + j + 1) * rsqrtf(__ldg(rv + j + 1) + 1e-5f);
        float sh0 = (__ldg(b1 + j)     - __ldg(rm + j))     * sc0 + __ldg(bt + j);
        float sh1 = (__ldg(b1 + j + 1) - __ldg(rm + j + 1)) * sc1 + __ldg(bt + j + 1);
        a = fmaxf(fmaf(a, sc0, sh0), 0.f);
        b = fmaxf(fmaf(b, sc1, sh1), 0.f);
        vals[j2] = pack2(a, b);
    }
}

// ---------------------------------------------------------------------------
// mlpB: h = relu( relu(BN(z + b1)) @ w2 + b2 )  (layer 1 tail; z = (x+agg)@w1)
// ---------------------------------------------------------------------------
__global__ __launch_bounds__(256) void mlpB_kernel(
    const float* __restrict__ z,
    const float* __restrict__ b1,
    const float* __restrict__ gg, const float* __restrict__ bt,
    const float* __restrict__ rm, const float* __restrict__ rv,
    const float* __restrict__ w2, const float* __restrict__ b2,
    float*       __restrict__ hout,
    const int*   __restrict__ batch,
    float*       __restrict__ pool, int pool_off, int n_nodes)
{
    __shared__ float ws[64 * 64];
    int tid = threadIdx.x;
    for (int i = tid; i < 64 * 64; i += 256) ws[i] = w2[i];
    __syncthreads();

    int t    = blockIdx.x * 256 + tid;
    int node = t >> 1, half = t & 1;
    bool active = node < n_nodes;
    int  nodec  = active ? node : (n_nodes - 1);
    int  halfoff = half * 32;

    // own 32 z values -> BN+ReLU -> hreg
    ull hreg[16];
    const float4* zrow = (const float4*)(z + (size_t)nodec * 64 + halfoff);
#pragma unroll
    for (int q = 0; q < 8; q++) {
        float4 v = __ldg(zrow + q);
        hreg[q * 2 + 0] = pack2(v.x, v.y);
        hreg[q * 2 + 1] = pack2(v.z, v.w);
    }
    bn_relu32(hreg, halfoff, b1, gg, bt, rm, rv);

    float* orow_base = hout + (size_t)node * 64;
    float* prow = active ? (pool + (size_t)__ldg(batch + node) * 192 + pool_off) : pool;
    gemm2_epilogue(ws, hreg, half, halfoff, b2, orow_base, prow, active);
}

// ---------------------------------------------------------------------------
// mlp64: full fused layer for layers 2/3.
// ---------------------------------------------------------------------------
__global__ __launch_bounds__(256) void mlp64_kernel(
    const float* __restrict__ agg,
    const float* __restrict__ w1, const float* __restrict__ b1,
    const float* __restrict__ gg, const float* __restrict__ bt,
    const float* __restrict__ rm, const float* __restrict__ rv,
    const float* __restrict__ w2, const float* __restrict__ b2,
    float*       __restrict__ hout,
    const int*   __restrict__ batch,
    float*       __restrict__ pool, int pool_off, int n_nodes)
{
    __shared__ float ws[64 * 64];
    int tid = threadIdx.x;
    for (int i = tid; i < 64 * 64; i += 256) ws[i] = w1[i];
    __syncthreads();

    int t    = blockIdx.x * 256 + tid;
    int node = t >> 1, half = t & 1;
    bool active = node < n_nodes;
    int  nodec  = active ? node : (n_nodes - 1);
    int  halfoff = half * 32;

    // own half of the 64-dim agg row
    float4 xv[8];
    const float4* arow = (const float4*)(agg + (size_t)nodec * 64) + half * 8;
#pragma unroll
    for (int q = 0; q < 8; q++) xv[q] = __ldg(arow + q);
    const float* xf = (const float*)xv;

    ull acc2[16];
#pragma unroll
    for (int j = 0; j < 16; j++) acc2[j] = 0ull;

#pragma unroll
    for (int kk2 = 0; kk2 < 16; kk2++) {
        float a0 = xf[kk2 * 2], a1 = xf[kk2 * 2 + 1];
        float b0 = __shfl_xor_sync(0xffffffffu, a0, 1);
        float b1 = __shfl_xor_sync(0xffffffffu, a1, 1);
        int kown = half * 32 + kk2 * 2;
        int kpar = (half ^ 1) * 32 + kk2 * 2;
        fma_k32(acc2, ws, kown,     halfoff, a0);
        fma_k32(acc2, ws, kown + 1, halfoff, a1);
        fma_k32(acc2, ws, kpar,     halfoff, b0);
        fma_k32(acc2, ws, kpar + 1, halfoff, b1);
    }

    bn_relu32(acc2, halfoff, b1, gg, bt, rm, rv);

    __syncthreads();
    for (int i = tid; i < 64 * 64; i += 256) ws[i] = w2[i];
    __syncthreads();

    float* orow_base = hout + (size_t)node * 64;
    float* prow = active ? (pool + (size_t)__ldg(batch + node) * 192 + pool_off) : pool;
    gemm2_epilogue(ws, acc2, half, halfoff, b2, orow_base, prow, active);
}

// ---------------------------------------------------------------------------
__global__ void final_kernel(const float* __restrict__ pool,
                             const float* __restrict__ lw1, const float* __restrict__ lb1,
                             const float* __restrict__ lw2, const float* __restrict__ lb2,
                             float* __restrict__ out)
{
    __shared__ float prow[192];
    __shared__ float hid[64];
    __shared__ float zz[2];
    int g = blockIdx.x, j = threadIdx.x;
    for (int k = j; k < 192; k += 64) prow[k] = pool[g * 192 + k];
    __syncthreads();
    float a = __ldg(lb1 + j);
    for (int k = 0; k < 192; k++) a = fmaf(prow[k], __ldg(lw1 + k * 64 + j), a);
    hid[j] = fmaxf(a, 0.f);
    __syncthreads();
    if (j < 2) {
        float z = __ldg(lb2 + j);
#pragma unroll 8
        for (int k = 0; k < 64; k++) z = fmaf(hid[k], __ldg(lw2 + k * 2 + j), z);
        zz[j] = z;
    }
    __syncthreads();
    if (j == 0) {
        float m   = fmaxf(zz[0], zz[1]);
        float lse = m + logf(expf(zz[0] - m) + expf(zz[1] - m));
        out[g * 2 + 0] = zz[0] - lse;
        out[g * 2 + 1] = zz[1] - lse;
    }
}

// ---------------------------------------------------------------------------
extern "C" void kernel_launch(void* const* d_in, const int* in_sizes, int n_in,
                              void* d_out, int out_size)
{
    const float* x     = (const float*)d_in[0];
    const int*   ei    = (const int*)  d_in[1];
    const int*   batch = (const int*)  d_in[2];

    int wi = (in_sizes[3] < 64) ? 4 : 3;
    const float* W[28];
    for (int i = 0; i < 28 && wi + i < n_in; i++) W[i] = (const float*)d_in[wi + i];

    int n_nodes = in_sizes[0] / 128;
    int n_edges = in_sizes[1] / 2;

    float *buf, *h1, *h2, *h3, *pool;
    int *deg, *row, *cur, *col, *bsum;
    cudaGetSymbolAddress((void**)&buf,  g_buf);
    cudaGetSymbolAddress((void**)&h1,   g_h1);
    cudaGetSymbolAddress((void**)&h2,   g_h2);
    cudaGetSymbolAddress((void**)&h3,   g_h3);
    cudaGetSymbolAddress((void**)&pool, g_pool);
    cudaGetSymbolAddress((void**)&deg,  g_deg);
    cudaGetSymbolAddress((void**)&row,  g_row);
    cudaGetSymbolAddress((void**)&cur,  g_cur);
    cudaGetSymbolAddress((void**)&col,  g_col);
    cudaGetSymbolAddress((void**)&bsum, g_bsum);

    float* y = buf;
    float* z = buf + (size_t)MAX_NODES * 64;
    float* out = (float*)d_out;

    int splitBlocks = (n_nodes * 2 + 255) / 256;     // 2 threads per node
    int pullBlocks  = (n_nodes * 16 + 255) / 256;
    int scanBlocks  = (n_nodes + SCAN_B - 1) / SCAN_B;

    // ---- CSR build ----
    zero_i_kernel<<<(n_nodes + 1 + 255) / 256, 256>>>(deg, n_nodes + 1);
    zero_f_kernel<<<(NGRAPH * 192 + 255) / 256, 256>>>(pool, NGRAPH * 192);
    hist_kernel<<<(n_edges + 255) / 256, 256>>>(ei, deg, n_edges);
    bsum_kernel<<<scanBlocks, SCAN_B>>>(deg, bsum, n_nodes);
    bscan_kernel<<<1, 32>>>(bsum, scanBlocks);
    scatter_scan_kernel<<<scanBlocks, SCAN_B>>>(deg, bsum, row, cur, n_nodes);
    fill_kernel<<<(n_edges + 255) / 256, 256>>>(ei, cur, col, n_edges);

    // ---- layer 1: y = x@w11 ; z = pull(y) ; h1 = mlpB(z) ----
    gemmA_kernel<<<splitBlocks, 256>>>(x, W[0], y, n_nodes);
    pull64_kernel<<<pullBlocks, 256>>>(y, row, col, z, n_nodes);
    mlpB_kernel<<<splitBlocks, 256>>>(z, W[1], W[2], W[3], W[4], W[5], W[6], W[7],
                                      h1, batch, pool, 0, n_nodes);

    // ---- layer 2 ----
    pull64_kernel<<<pullBlocks, 256>>>(h1, row, col, z, n_nodes);
    mlp64_kernel<<<splitBlocks, 256>>>(z, W[8], W[9], W[10], W[11], W[12], W[13], W[14], W[15],
                                       h2, batch, pool, 64, n_nodes);

    // ---- layer 3 ----
    pull64_kernel<<<pullBlocks, 256>>>(h2, row, col, z, n_nodes);
    mlp64_kernel<<<splitBlocks, 256>>>(z, W[16], W[17], W[18], W[19], W[20], W[21], W[22], W[23],
                                       h3, batch, pool, 128, n_nodes);

    final_kernel<<<NGRAPH, 64>>>(pool, W[24], W[25], W[26], W[27], out);
}

// round 6
// speedup vs baseline: 1.3419x; 1.3419x over previous
#include <cuda_runtime.h>
#include <math.h>

// ---------------------------------------------------------------------------
// GIN (3 GINConv layers + BN + ReLU + MLP head)
//   N_NODES=100000, N_EDGES=1200000, D_IN=128, D_H=64, N_GRAPHS=256
// R5 changes vs R4 (which regressed; SHFL exchange abandoned):
//   * MLP kernels: 2 nodes per thread, j-split 2 (32 cols/thread).
//     One weight LDS stream serves both nodes -> per-node instrs ~2.3x fewer.
//   * GEMM1->GEMM2 handoff via 32KB smem tile [col][node] (no shuffles).
//   * pull64 / CSR build / final head unchanged from the 497us version.
// ---------------------------------------------------------------------------

#define MAX_NODES 100000
#define MAX_EDGES 1200000
#define NGRAPH    256
#define SCAN_B    1024
#define MAX_SCAN_BLOCKS 128

__device__ float g_buf [MAX_NODES * 128];     // y | z
__device__ float g_h1  [MAX_NODES * 64];
__device__ float g_h2  [MAX_NODES * 64];
__device__ float g_h3  [MAX_NODES * 64];
__device__ float g_pool[NGRAPH * 192];
__device__ int   g_deg [MAX_NODES + 1];
__device__ int   g_row [MAX_NODES + 1];
__device__ int   g_cur [MAX_NODES];
__device__ int   g_col [MAX_EDGES];
__device__ int   g_bsum[MAX_SCAN_BLOCKS];

typedef unsigned long long ull;

__device__ __forceinline__ ull pack2(float lo, float hi) {
    ull r; asm("mov.b64 %0,{%1,%2};" : "=l"(r) : "f"(lo), "f"(hi)); return r;
}
__device__ __forceinline__ void unpack2(ull v, float& lo, float& hi) {
    asm("mov.b64 {%0,%1},%2;" : "=f"(lo), "=f"(hi) : "l"(v));
}
__device__ __forceinline__ ull fma2(ull a, ull b, ull c) {
    ull d; asm("fma.rn.f32x2 %0,%1,%2,%3;" : "=l"(d) : "l"(a), "l"(b), "l"(c)); return d;
}

// One k-step: one weight row segment (32 cols) feeds TWO nodes' accumulators.
__device__ __forceinline__ void fma_k32_dual(ull* accA, ull* accB,
                                             const float* ws, int k, int halfoff,
                                             float va, float vb) {
    ull a2 = pack2(va, va), b2 = pack2(vb, vb);
    const ulonglong2* wrow = (const ulonglong2*)(ws + k * 64 + halfoff);
#pragma unroll
    for (int j8 = 0; j8 < 8; j8++) {
        ulonglong2 wv = wrow[j8];
        accA[j8 * 2 + 0] = fma2(a2, wv.x, accA[j8 * 2 + 0]);
        accA[j8 * 2 + 1] = fma2(a2, wv.y, accA[j8 * 2 + 1]);
        accB[j8 * 2 + 0] = fma2(b2, wv.x, accB[j8 * 2 + 0]);
        accB[j8 * 2 + 1] = fma2(b2, wv.y, accB[j8 * 2 + 1]);
    }
}

// BN(eval)+ReLU for col pair (j, j+1) applied to both nodes' packed values.
__device__ __forceinline__ void bn_pair(ull& va, ull& vb, int j,
    const float* __restrict__ b1, const float* __restrict__ gg,
    const float* __restrict__ bt, const float* __restrict__ rm,
    const float* __restrict__ rv)
{
    float sc0 = __ldg(gg + j)     * rsqrtf(__ldg(rv + j)     + 1e-5f);
    float sc1 = __ldg(gg + j + 1) * rsqrtf(__ldg(rv + j + 1) + 1e-5f);
    float sh0 = (__ldg(b1 + j)     - __ldg(rm + j))     * sc0 + __ldg(bt + j);
    float sh1 = (__ldg(b1 + j + 1) - __ldg(rm + j + 1)) * sc1 + __ldg(bt + j + 1);
    float a, b;
    unpack2(va, a, b);
    a = fmaxf(fmaf(a, sc0, sh0), 0.f);
    b = fmaxf(fmaf(b, sc1, sh1), 0.f);
    va = pack2(a, b);
    unpack2(vb, a, b);
    a = fmaxf(fmaf(a, sc0, sh0), 0.f);
    b = fmaxf(fmaf(b, sc1, sh1), 0.f);
    vb = pack2(a, b);
}

// Epilogue for one node's 32 cols: bias + ReLU + store + pool reduction.
__device__ __forceinline__ void epi_node(const ull* out16, int halfoff,
                                         const float* __restrict__ b2,
                                         float* orow, float* prow, bool act)
{
    if (!act) return;
    float4* o4 = (float4*)(orow + halfoff);
#pragma unroll
    for (int qq = 0; qq < 8; qq++) {
        int j = halfoff + qq * 4;
        float a0, a1, a2, a3;
        unpack2(out16[qq * 2 + 0], a0, a1);
        unpack2(out16[qq * 2 + 1], a2, a3);
        float4 v;
        v.x = fmaxf(a0 + __ldg(b2 + j + 0), 0.f);
        v.y = fmaxf(a1 + __ldg(b2 + j + 1), 0.f);
        v.z = fmaxf(a2 + __ldg(b2 + j + 2), 0.f);
        v.w = fmaxf(a3 + __ldg(b2 + j + 3), 0.f);
        o4[qq] = v;
        asm volatile("red.global.add.v4.f32 [%0], {%1,%2,%3,%4};"
                     :: "l"(prow + j), "f"(v.x), "f"(v.y), "f"(v.z), "f"(v.w)
                     : "memory");
    }
}

// ---------------------------------------------------------------------------
__global__ void zero_f_kernel(float* __restrict__ p, int n) {
    int i = blockIdx.x * blockDim.x + threadIdx.x;
    if (i < n) p[i] = 0.f;
}
__global__ void zero_i_kernel(int* __restrict__ p, int n) {
    int i = blockIdx.x * blockDim.x + threadIdx.x;
    if (i < n) p[i] = 0;
}

// ---------------------------------------------------------------------------
// CSR build
// ---------------------------------------------------------------------------
__global__ void hist_kernel(const int* __restrict__ ei, int* __restrict__ deg, int n_edges) {
    int e = blockIdx.x * blockDim.x + threadIdx.x;
    if (e < n_edges) atomicAdd(deg + __ldg(ei + n_edges + e), 1);
}

__global__ void bsum_kernel(const int* __restrict__ deg, int* __restrict__ bsum, int n) {
    __shared__ int sm[SCAN_B];
    int i = blockIdx.x * SCAN_B + threadIdx.x;
    sm[threadIdx.x] = (i < n) ? deg[i] : 0;
    __syncthreads();
#pragma unroll
    for (int off = SCAN_B / 2; off > 0; off >>= 1) {
        if (threadIdx.x < off) sm[threadIdx.x] += sm[threadIdx.x + off];
        __syncthreads();
    }
    if (threadIdx.x == 0) bsum[blockIdx.x] = sm[0];
}

__global__ void bscan_kernel(int* __restrict__ bsum, int nb) {
    if (threadIdx.x == 0) {
        int run = 0;
        for (int i = 0; i < nb; i++) { int v = bsum[i]; bsum[i] = run; run += v; }
    }
}

__global__ void scatter_scan_kernel(const int* __restrict__ deg,
                                    const int* __restrict__ bsum,
                                    int* __restrict__ rowptr, int* __restrict__ cur, int n) {
    __shared__ int sm[SCAN_B];
    int i = blockIdx.x * SCAN_B + threadIdx.x;
    int v = (i < n) ? deg[i] : 0;
    sm[threadIdx.x] = v;
    __syncthreads();
#pragma unroll
    for (int off = 1; off < SCAN_B; off *= 2) {
        int t = (threadIdx.x >= off) ? sm[threadIdx.x - off] : 0;
        __syncthreads();
        sm[threadIdx.x] += t;
        __syncthreads();
    }
    int excl = sm[threadIdx.x] - v + bsum[blockIdx.x];
    if (i < n) { rowptr[i] = excl; cur[i] = excl; }
    if (i == n - 1) rowptr[n] = excl + v;
}

__global__ void fill_kernel(const int* __restrict__ ei, int* __restrict__ cur,
                            int* __restrict__ col, int n_edges) {
    int e = blockIdx.x * blockDim.x + threadIdx.x;
    if (e >= n_edges) return;
    int s = __ldg(ei + e);
    int d = __ldg(ei + n_edges + e);
    int pos = atomicAdd(cur + d, 1);
    col[pos] = s;
}

// ---------------------------------------------------------------------------
// Pull aggregation: out[i] = in[i] + sum_{j in nb(i)} in[j]; 16 thr/node.
// ---------------------------------------------------------------------------
__global__ void pull64_kernel(const float* __restrict__ hin,
                              const int* __restrict__ rowptr,
                              const int* __restrict__ col,
                              float* __restrict__ hout, int n_nodes) {
    int t = blockIdx.x * blockDim.x + threadIdx.x;
    int node = t >> 4, lane = t & 15;
    if (node >= n_nodes) return;
    const float4* base = (const float4*)hin;
    float4 acc = __ldg(base + (size_t)node * 16 + lane);
    int e   = __ldg(rowptr + node);
    int end = __ldg(rowptr + node + 1);
    for (; e + 8 <= end; e += 8) {
        int s0 = __ldg(col + e),     s1 = __ldg(col + e + 1);
        int s2 = __ldg(col + e + 2), s3 = __ldg(col + e + 3);
        int s4 = __ldg(col + e + 4), s5 = __ldg(col + e + 5);
        int s6 = __ldg(col + e + 6), s7 = __ldg(col + e + 7);
        float4 v0 = __ldg(base + (size_t)s0 * 16 + lane);
        float4 v1 = __ldg(base + (size_t)s1 * 16 + lane);
        float4 v2 = __ldg(base + (size_t)s2 * 16 + lane);
        float4 v3 = __ldg(base + (size_t)s3 * 16 + lane);
        float4 v4 = __ldg(base + (size_t)s4 * 16 + lane);
        float4 v5 = __ldg(base + (size_t)s5 * 16 + lane);
        float4 v6 = __ldg(base + (size_t)s6 * 16 + lane);
        float4 v7 = __ldg(base + (size_t)s7 * 16 + lane);
        acc.x += ((v0.x + v1.x) + (v2.x + v3.x)) + ((v4.x + v5.x) + (v6.x + v7.x));
        acc.y += ((v0.y + v1.y) + (v2.y + v3.y)) + ((v4.y + v5.y) + (v6.y + v7.y));
        acc.z += ((v0.z + v1.z) + (v2.z + v3.z)) + ((v4.z + v5.z) + (v6.z + v7.z));
        acc.w += ((v0.w + v1.w) + (v2.w + v3.w)) + ((v4.w + v5.w) + (v6.w + v7.w));
    }
    for (; e + 4 <= end; e += 4) {
        int s0 = __ldg(col + e),     s1 = __ldg(col + e + 1);
        int s2 = __ldg(col + e + 2), s3 = __ldg(col + e + 3);
        float4 v0 = __ldg(base + (size_t)s0 * 16 + lane);
        float4 v1 = __ldg(base + (size_t)s1 * 16 + lane);
        float4 v2 = __ldg(base + (size_t)s2 * 16 + lane);
        float4 v3 = __ldg(base + (size_t)s3 * 16 + lane);
        acc.x += (v0.x + v1.x) + (v2.x + v3.x);
        acc.y += (v0.y + v1.y) + (v2.y + v3.y);
        acc.z += (v0.z + v1.z) + (v2.z + v3.z);
        acc.w += (v0.w + v1.w) + (v2.w + v3.w);
    }
    for (; e < end; e++) {
        int s = __ldg(col + e);
        float4 v = __ldg(base + (size_t)s * 16 + lane);
        acc.x += v.x; acc.y += v.y; acc.z += v.z; acc.w += v.w;
    }
    ((float4*)hout)[(size_t)node * 16 + lane] = acc;
}

// ---------------------------------------------------------------------------
// gemmA: y = x @ w1  (x: [N,128] -> y: [N,64]).
// 128 threads/block, 128 nodes/block: thread handles 2 nodes x 32 cols.
// ---------------------------------------------------------------------------
__global__ __launch_bounds__(128) void gemmA_kernel(
    const float* __restrict__ x, const float* __restrict__ w1,
    float* __restrict__ y, int n_nodes)
{
    __shared__ float ws[128 * 64];   // 32KB
    int tid = threadIdx.x;
    for (int i = tid; i < 128 * 64; i += 128) ws[i] = w1[i];
    __syncthreads();

    int half = tid & 1, q = tid >> 1;
    int halfoff = half * 32;
    int n0 = blockIdx.x * 128 + 2 * q, n1 = n0 + 1;
    bool a0 = n0 < n_nodes, a1 = n1 < n_nodes;
    int n0c = a0 ? n0 : n_nodes - 1, n1c = a1 ? n1 : n_nodes - 1;

    ull acc[2][16];
#pragma unroll
    for (int j = 0; j < 16; j++) { acc[0][j] = 0ull; acc[1][j] = 0ull; }

    const float4* r0 = (const float4*)(x + (size_t)n0c * 128);
    const float4* r1 = (const float4*)(x + (size_t)n1c * 128);
#pragma unroll 4
    for (int k4 = 0; k4 < 32; k4++) {
        float4 v0 = __ldg(r0 + k4), v1 = __ldg(r1 + k4);
        float f0[4] = {v0.x, v0.y, v0.z, v0.w};
        float f1[4] = {v1.x, v1.y, v1.z, v1.w};
#pragma unroll
        for (int kk = 0; kk < 4; kk++)
            fma_k32_dual(acc[0], acc[1], ws, k4 * 4 + kk, halfoff, f0[kk], f1[kk]);
    }

#pragma unroll
    for (int nd = 0; nd < 2; nd++) {
        bool act = nd ? a1 : a0;
        if (!act) continue;
        int n = nd ? n1 : n0;
        float4* orow = (float4*)(y + (size_t)n * 64 + halfoff);
#pragma unroll
        for (int qq = 0; qq < 8; qq++) {
            float a, b, c, d;
            unpack2(acc[nd][qq * 2 + 0], a, b);
            unpack2(acc[nd][qq * 2 + 1], c, d);
            orow[qq] = make_float4(a, b, c, d);
        }
    }
}

// ---------------------------------------------------------------------------
// mlpB (layer-1 tail): h = relu( relu(BN(z + b1)) @ w2 + b2 ); store + pool.
// 2 nodes/thread, smem tile handoff.
// ---------------------------------------------------------------------------
__global__ __launch_bounds__(128) void mlpB_kernel(
    const float* __restrict__ z,
    const float* __restrict__ b1,
    const float* __restrict__ gg, const float* __restrict__ bt,
    const float* __restrict__ rm, const float* __restrict__ rv,
    const float* __restrict__ w2, const float* __restrict__ b2,
    float*       __restrict__ hout,
    const int*   __restrict__ batch,
    float*       __restrict__ pool, int pool_off, int n_nodes)
{
    __shared__ float ws[64 * 64];      // 16KB (w2)
    __shared__ float tile[64 * 128];   // 32KB [col][node]
    int tid = threadIdx.x;
    for (int i = tid; i < 64 * 64; i += 128) ws[i] = w2[i];

    int half = tid & 1, q = tid >> 1;
    int halfoff = half * 32;
    int n0 = blockIdx.x * 128 + 2 * q, n1 = n0 + 1;
    bool a0 = n0 < n_nodes, a1 = n1 < n_nodes;
    int n0c = a0 ? n0 : n_nodes - 1, n1c = a1 ? n1 : n_nodes - 1;

    // load own 32 cols of both z rows, BN+ReLU, write to tile
    const float4* zr0 = (const float4*)(z + (size_t)n0c * 64 + halfoff);
    const float4* zr1 = (const float4*)(z + (size_t)n1c * 64 + halfoff);
#pragma unroll
    for (int qq = 0; qq < 8; qq++) {
        float4 v0 = __ldg(zr0 + qq), v1 = __ldg(zr1 + qq);
        ull p00 = pack2(v0.x, v0.y), p01 = pack2(v0.z, v0.w);
        ull p10 = pack2(v1.x, v1.y), p11 = pack2(v1.z, v1.w);
        int j = halfoff + qq * 4;
        bn_pair(p00, p10, j,     b1, gg, bt, rm, rv);
        bn_pair(p01, p11, j + 2, b1, gg, bt, rm, rv);
        float x0, x1, y0, y1;
        unpack2(p00, x0, x1); unpack2(p10, y0, y1);
        *(float2*)&tile[(j + 0) * 128 + 2 * q] = make_float2(x0, y0);
        *(float2*)&tile[(j + 1) * 128 + 2 * q] = make_float2(x1, y1);
        unpack2(p01, x0, x1); unpack2(p11, y0, y1);
        *(float2*)&tile[(j + 2) * 128 + 2 * q] = make_float2(x0, y0);
        *(float2*)&tile[(j + 3) * 128 + 2 * q] = make_float2(x1, y1);
    }
    __syncthreads();

    ull out[2][16];
#pragma unroll
    for (int j = 0; j < 16; j++) { out[0][j] = 0ull; out[1][j] = 0ull; }
#pragma unroll 4
    for (int k = 0; k < 64; k++) {
        float2 hv = *(const float2*)&tile[k * 128 + 2 * q];
        fma_k32_dual(out[0], out[1], ws, k, halfoff, hv.x, hv.y);
    }

    float* o0 = hout + (size_t)n0 * 64;
    float* o1 = hout + (size_t)n1 * 64;
    float* p0 = a0 ? (pool + (size_t)__ldg(batch + n0) * 192 + pool_off) : pool;
    float* p1 = a1 ? (pool + (size_t)__ldg(batch + n1) * 192 + pool_off) : pool;
    epi_node(out[0], halfoff, b2, o0, p0, a0);
    epi_node(out[1], halfoff, b2, o1, p1, a1);
}

// ---------------------------------------------------------------------------
// mlp64: full fused layer (layers 2/3). 2 nodes/thread, smem tile handoff.
// ---------------------------------------------------------------------------
__global__ __launch_bounds__(128) void mlp64_kernel(
    const float* __restrict__ agg,
    const float* __restrict__ w1, const float* __restrict__ b1,
    const float* __restrict__ gg, const float* __restrict__ bt,
    const float* __restrict__ rm, const float* __restrict__ rv,
    const float* __restrict__ w2, const float* __restrict__ b2,
    float*       __restrict__ hout,
    const int*   __restrict__ batch,
    float*       __restrict__ pool, int pool_off, int n_nodes)
{
    __shared__ float ws[64 * 64];      // 16KB (w1 then w2)
    __shared__ float tile[64 * 128];   // 32KB [col][node]
    int tid = threadIdx.x;
    for (int i = tid; i < 64 * 64; i += 128) ws[i] = w1[i];
    __syncthreads();

    int half = tid & 1, q = tid >> 1;
    int halfoff = half * 32;
    int n0 = blockIdx.x * 128 + 2 * q, n1 = n0 + 1;
    bool a0 = n0 < n_nodes, a1 = n1 < n_nodes;
    int n0c = a0 ? n0 : n_nodes - 1, n1c = a1 ? n1 : n_nodes - 1;

    // ---- GEMM1 ----
    ull acc[2][16];
#pragma unroll
    for (int j = 0; j < 16; j++) { acc[0][j] = 0ull; acc[1][j] = 0ull; }

    const float4* r0 = (const float4*)(agg + (size_t)n0c * 64);
    const float4* r1 = (const float4*)(agg + (size_t)n1c * 64);
#pragma unroll 4
    for (int k4 = 0; k4 < 16; k4++) {
        float4 v0 = __ldg(r0 + k4), v1 = __ldg(r1 + k4);
        float f0[4] = {v0.x, v0.y, v0.z, v0.w};
        float f1[4] = {v1.x, v1.y, v1.z, v1.w};
#pragma unroll
        for (int kk = 0; kk < 4; kk++)
            fma_k32_dual(acc[0], acc[1], ws, k4 * 4 + kk, halfoff, f0[kk], f1[kk]);
    }

    // ---- BN + ReLU -> tile ----
#pragma unroll
    for (int j2 = 0; j2 < 16; j2++) {
        int j = halfoff + 2 * j2;
        bn_pair(acc[0][j2], acc[1][j2], j, b1, gg, bt, rm, rv);
        float x0, x1, y0, y1;
        unpack2(acc[0][j2], x0, x1);
        unpack2(acc[1][j2], y0, y1);
        *(float2*)&tile[(j + 0) * 128 + 2 * q] = make_float2(x0, y0);
        *(float2*)&tile[(j + 1) * 128 + 2 * q] = make_float2(x1, y1);
    }

    // ---- swap weights ----
    __syncthreads();
    for (int i = tid; i < 64 * 64; i += 128) ws[i] = w2[i];
    __syncthreads();

    // ---- GEMM2 ----
    ull out[2][16];
#pragma unroll
    for (int j = 0; j < 16; j++) { out[0][j] = 0ull; out[1][j] = 0ull; }
#pragma unroll 4
    for (int k = 0; k < 64; k++) {
        float2 hv = *(const float2*)&tile[k * 128 + 2 * q];
        fma_k32_dual(out[0], out[1], ws, k, halfoff, hv.x, hv.y);
    }

    float* o0 = hout + (size_t)n0 * 64;
    float* o1 = hout + (size_t)n1 * 64;
    float* p0 = a0 ? (pool + (size_t)__ldg(batch + n0) * 192 + pool_off) : pool;
    float* p1 = a1 ? (pool + (size_t)__ldg(batch + n1) * 192 + pool_off) : pool;
    epi_node(out[0], halfoff, b2, o0, p0, a0);
    epi_node(out[1], halfoff, b2, o1, p1, a1);
}

// ---------------------------------------------------------------------------
__global__ void final_kernel(const float* __restrict__ pool,
                             const float* __restrict__ lw1, const float* __restrict__ lb1,
                             const float* __restrict__ lw2, const float* __restrict__ lb2,
                             float* __restrict__ out)
{
    __shared__ float prow[192];
    __shared__ float hid[64];
    __shared__ float zz[2];
    int g = blockIdx.x, j = threadIdx.x;
    for (int k = j; k < 192; k += 64) prow[k] = pool[g * 192 + k];
    __syncthreads();
    float a = __ldg(lb1 + j);
    for (int k = 0; k < 192; k++) a = fmaf(prow[k], __ldg(lw1 + k * 64 + j), a);
    hid[j] = fmaxf(a, 0.f);
    __syncthreads();
    if (j < 2) {
        float z = __ldg(lb2 + j);
#pragma unroll 8
        for (int k = 0; k < 64; k++) z = fmaf(hid[k], __ldg(lw2 + k * 2 + j), z);
        zz[j] = z;
    }
    __syncthreads();
    if (j == 0) {
        float m   = fmaxf(zz[0], zz[1]);
        float lse = m + logf(expf(zz[0] - m) + expf(zz[1] - m));
        out[g * 2 + 0] = zz[0] - lse;
        out[g * 2 + 1] = zz[1] - lse;
    }
}

// ---------------------------------------------------------------------------
extern "C" void kernel_launch(void* const* d_in, const int* in_sizes, int n_in,
                              void* d_out, int out_size)
{
    const float* x     = (const float*)d_in[0];
    const int*   ei    = (const int*)  d_in[1];
    const int*   batch = (const int*)  d_in[2];

    int wi = (in_sizes[3] < 64) ? 4 : 3;
    const float* W[28];
    for (int i = 0; i < 28 && wi + i < n_in; i++) W[i] = (const float*)d_in[wi + i];

    int n_nodes = in_sizes[0] / 128;
    int n_edges = in_sizes[1] / 2;

    float *buf, *h1, *h2, *h3, *pool;
    int *deg, *row, *cur, *col, *bsum;
    cudaGetSymbolAddress((void**)&buf,  g_buf);
    cudaGetSymbolAddress((void**)&h1,   g_h1);
    cudaGetSymbolAddress((void**)&h2,   g_h2);
    cudaGetSymbolAddress((void**)&h3,   g_h3);
    cudaGetSymbolAddress((void**)&pool, g_pool);
    cudaGetSymbolAddress((void**)&deg,  g_deg);
    cudaGetSymbolAddress((void**)&row,  g_row);
    cudaGetSymbolAddress((void**)&cur,  g_cur);
    cudaGetSymbolAddress((void**)&col,  g_col);
    cudaGetSymbolAddress((void**)&bsum, g_bsum);

    float* y = buf;
    float* z = buf + (size_t)MAX_NODES * 64;
    float* out = (float*)d_out;

    int mlpBlocks  = (n_nodes + 127) / 128;          // 128 nodes per block
    int pullBlocks = (n_nodes * 16 + 255) / 256;
    int scanBlocks = (n_nodes + SCAN_B - 1) / SCAN_B;

    // ---- CSR build ----
    zero_i_kernel<<<(n_nodes + 1 + 255) / 256, 256>>>(deg, n_nodes + 1);
    zero_f_kernel<<<(NGRAPH * 192 + 255) / 256, 256>>>(pool, NGRAPH * 192);
    hist_kernel<<<(n_edges + 255) / 256, 256>>>(ei, deg, n_edges);
    bsum_kernel<<<scanBlocks, SCAN_B>>>(deg, bsum, n_nodes);
    bscan_kernel<<<1, 32>>>(bsum, scanBlocks);
    scatter_scan_kernel<<<scanBlocks, SCAN_B>>>(deg, bsum, row, cur, n_nodes);
    fill_kernel<<<(n_edges + 255) / 256, 256>>>(ei, cur, col, n_edges);

    // ---- layer 1: y = x@w11 ; z = pull(y) ; h1 = mlpB(z) ----
    gemmA_kernel<<<mlpBlocks, 128>>>(x, W[0], y, n_nodes);
    pull64_kernel<<<pullBlocks, 256>>>(y, row, col, z, n_nodes);
    mlpB_kernel<<<mlpBlocks, 128>>>(z, W[1], W[2], W[3], W[4], W[5], W[6], W[7],
                                    h1, batch, pool, 0, n_nodes);

    // ---- layer 2 ----
    pull64_kernel<<<pullBlocks, 256>>>(h1, row, col, z, n_nodes);
    mlp64_kernel<<<mlpBlocks, 128>>>(z, W[8], W[9], W[10], W[11], W[12], W[13], W[14], W[15],
                                     h2, batch, pool, 64, n_nodes);

    // ---- layer 3 ----
    pull64_kernel<<<pullBlocks, 256>>>(h2, row, col, z, n_nodes);
    mlp64_kernel<<<mlpBlocks, 128>>>(z, W[16], W[17], W[18], W[19], W[20], W[21], W[22], W[23],
                                     h3, batch, pool, 128, n_nodes);

    final_kernel<<<NGRAPH, 64>>>(pool, W[24], W[25], W[26], W[27], out);
}

// round 7
// speedup vs baseline: 1.4306x; 1.0661x over previous
#include <cuda_runtime.h>
#include <cuda_fp16.h>
#include <math.h>

// ---------------------------------------------------------------------------
// GIN (3 GINConv layers + BN + ReLU + MLP head)
//   N_NODES=100000, N_EDGES=1200000, D_IN=128, D_H=64, N_GRAPHS=256
// R6 changes vs R5:
//   * activations gathered by pull are stored ONLY as fp16 (128B/row):
//     gather traffic halved, fp32 h/y write streams eliminated.
//     pull accumulates fp32 and emits fp32 z; MLP math unchanged (fp32).
// ---------------------------------------------------------------------------

#define MAX_NODES 100000
#define MAX_EDGES 1200000
#define NGRAPH    256
#define SCAN_B    1024
#define MAX_SCAN_BLOCKS 128

__device__ float g_z   [MAX_NODES * 64];    // fp32 aggregated rows (pull output)
__device__ uint2 g_hh  [MAX_NODES * 16];    // fp16 activation rows (128B/node)
__device__ float g_pool[NGRAPH * 192];
__device__ int   g_deg [MAX_NODES + 1];
__device__ int   g_row [MAX_NODES + 1];
__device__ int   g_cur [MAX_NODES];
__device__ int   g_col [MAX_EDGES];
__device__ int   g_bsum[MAX_SCAN_BLOCKS];

typedef unsigned long long ull;

__device__ __forceinline__ ull pack2(float lo, float hi) {
    ull r; asm("mov.b64 %0,{%1,%2};" : "=l"(r) : "f"(lo), "f"(hi)); return r;
}
__device__ __forceinline__ void unpack2(ull v, float& lo, float& hi) {
    asm("mov.b64 {%0,%1},%2;" : "=f"(lo), "=f"(hi) : "l"(v));
}
__device__ __forceinline__ ull fma2(ull a, ull b, ull c) {
    ull d; asm("fma.rn.f32x2 %0,%1,%2,%3;" : "=l"(d) : "l"(a), "l"(b), "l"(c)); return d;
}
__device__ __forceinline__ float4 h2f4(uint2 u) {
    __half2 a = *(__half2*)&u.x, b = *(__half2*)&u.y;
    float2 fa = __half22float2(a), fb = __half22float2(b);
    return make_float4(fa.x, fa.y, fb.x, fb.y);
}
__device__ __forceinline__ uint2 f4h(float a, float b, float c, float d) {
    __half2 lo = __floats2half2_rn(a, b), hi = __floats2half2_rn(c, d);
    uint2 u; u.x = *(unsigned*)&lo; u.y = *(unsigned*)&hi; return u;
}

// One k-step: one weight row segment (32 cols) feeds TWO nodes' accumulators.
__device__ __forceinline__ void fma_k32_dual(ull* accA, ull* accB,
                                             const float* ws, int k, int halfoff,
                                             float va, float vb) {
    ull a2 = pack2(va, va), b2 = pack2(vb, vb);
    const ulonglong2* wrow = (const ulonglong2*)(ws + k * 64 + halfoff);
#pragma unroll
    for (int j8 = 0; j8 < 8; j8++) {
        ulonglong2 wv = wrow[j8];
        accA[j8 * 2 + 0] = fma2(a2, wv.x, accA[j8 * 2 + 0]);
        accA[j8 * 2 + 1] = fma2(a2, wv.y, accA[j8 * 2 + 1]);
        accB[j8 * 2 + 0] = fma2(b2, wv.x, accB[j8 * 2 + 0]);
        accB[j8 * 2 + 1] = fma2(b2, wv.y, accB[j8 * 2 + 1]);
    }
}

// BN(eval)+ReLU for col pair (j, j+1) applied to both nodes' packed values.
__device__ __forceinline__ void bn_pair(ull& va, ull& vb, int j,
    const float* __restrict__ b1, const float* __restrict__ gg,
    const float* __restrict__ bt, const float* __restrict__ rm,
    const float* __restrict__ rv)
{
    float sc0 = __ldg(gg + j)     * rsqrtf(__ldg(rv + j)     + 1e-5f);
    float sc1 = __ldg(gg + j + 1) * rsqrtf(__ldg(rv + j + 1) + 1e-5f);
    float sh0 = (__ldg(b1 + j)     - __ldg(rm + j))     * sc0 + __ldg(bt + j);
    float sh1 = (__ldg(b1 + j + 1) - __ldg(rm + j + 1)) * sc1 + __ldg(bt + j + 1);
    float a, b;
    unpack2(va, a, b);
    a = fmaxf(fmaf(a, sc0, sh0), 0.f);
    b = fmaxf(fmaf(b, sc1, sh1), 0.f);
    va = pack2(a, b);
    unpack2(vb, a, b);
    a = fmaxf(fmaf(a, sc0, sh0), 0.f);
    b = fmaxf(fmaf(b, sc1, sh1), 0.f);
    vb = pack2(a, b);
}

// Epilogue for one node's 32 cols: bias + ReLU + fp16 store + pool reduction.
__device__ __forceinline__ void epi_node(const ull* out16, int halfoff,
                                         const float* __restrict__ b2,
                                         uint2* hrow, float* prow, bool act)
{
    if (!act) return;
    int ubase = halfoff >> 2;   // uint2 unit index (4 halves per uint2)
#pragma unroll
    for (int qq = 0; qq < 8; qq++) {
        int j = halfoff + qq * 4;
        float a0, a1, a2, a3;
        unpack2(out16[qq * 2 + 0], a0, a1);
        unpack2(out16[qq * 2 + 1], a2, a3);
        a0 = fmaxf(a0 + __ldg(b2 + j + 0), 0.f);
        a1 = fmaxf(a1 + __ldg(b2 + j + 1), 0.f);
        a2 = fmaxf(a2 + __ldg(b2 + j + 2), 0.f);
        a3 = fmaxf(a3 + __ldg(b2 + j + 3), 0.f);
        hrow[ubase + qq] = f4h(a0, a1, a2, a3);
        asm volatile("red.global.add.v4.f32 [%0], {%1,%2,%3,%4};"
                     :: "l"(prow + j), "f"(a0), "f"(a1), "f"(a2), "f"(a3)
                     : "memory");
    }
}

// ---------------------------------------------------------------------------
__global__ void zero_f_kernel(float* __restrict__ p, int n) {
    int i = blockIdx.x * blockDim.x + threadIdx.x;
    if (i < n) p[i] = 0.f;
}
__global__ void zero_i_kernel(int* __restrict__ p, int n) {
    int i = blockIdx.x * blockDim.x + threadIdx.x;
    if (i < n) p[i] = 0;
}

// ---------------------------------------------------------------------------
// CSR build
// ---------------------------------------------------------------------------
__global__ void hist_kernel(const int* __restrict__ ei, int* __restrict__ deg, int n_edges) {
    int e = blockIdx.x * blockDim.x + threadIdx.x;
    if (e < n_edges) atomicAdd(deg + __ldg(ei + n_edges + e), 1);
}

__global__ void bsum_kernel(const int* __restrict__ deg, int* __restrict__ bsum, int n) {
    __shared__ int sm[SCAN_B];
    int i = blockIdx.x * SCAN_B + threadIdx.x;
    sm[threadIdx.x] = (i < n) ? deg[i] : 0;
    __syncthreads();
#pragma unroll
    for (int off = SCAN_B / 2; off > 0; off >>= 1) {
        if (threadIdx.x < off) sm[threadIdx.x] += sm[threadIdx.x + off];
        __syncthreads();
    }
    if (threadIdx.x == 0) bsum[blockIdx.x] = sm[0];
}

__global__ void bscan_kernel(int* __restrict__ bsum, int nb) {
    if (threadIdx.x == 0) {
        int run = 0;
        for (int i = 0; i < nb; i++) { int v = bsum[i]; bsum[i] = run; run += v; }
    }
}

__global__ void scatter_scan_kernel(const int* __restrict__ deg,
                                    const int* __restrict__ bsum,
                                    int* __restrict__ rowptr, int* __restrict__ cur, int n) {
    __shared__ int sm[SCAN_B];
    int i = blockIdx.x * SCAN_B + threadIdx.x;
    int v = (i < n) ? deg[i] : 0;
    sm[threadIdx.x] = v;
    __syncthreads();
#pragma unroll
    for (int off = 1; off < SCAN_B; off *= 2) {
        int t = (threadIdx.x >= off) ? sm[threadIdx.x - off] : 0;
        __syncthreads();
        sm[threadIdx.x] += t;
        __syncthreads();
    }
    int excl = sm[threadIdx.x] - v + bsum[blockIdx.x];
    if (i < n) { rowptr[i] = excl; cur[i] = excl; }
    if (i == n - 1) rowptr[n] = excl + v;
}

__global__ void fill_kernel(const int* __restrict__ ei, int* __restrict__ cur,
                            int* __restrict__ col, int n_edges) {
    int e = blockIdx.x * blockDim.x + threadIdx.x;
    if (e >= n_edges) return;
    int s = __ldg(ei + e);
    int d = __ldg(ei + n_edges + e);
    int pos = atomicAdd(cur + d, 1);
    col[pos] = s;
}

// ---------------------------------------------------------------------------
// Pull aggregation over fp16 rows: z[i] = hh[i] + sum_{j in nb(i)} hh[j],
// fp32 accumulation, fp32 output. 16 threads/node, 8B (4 halves) per lane.
// ---------------------------------------------------------------------------
__global__ void pull64h_kernel(const uint2* __restrict__ hh,
                               const int* __restrict__ rowptr,
                               const int* __restrict__ col,
                               float* __restrict__ zout, int n_nodes) {
    int t = blockIdx.x * blockDim.x + threadIdx.x;
    int node = t >> 4, lane = t & 15;
    if (node >= n_nodes) return;
    float4 acc = h2f4(__ldg(hh + (size_t)node * 16 + lane));
    int e   = __ldg(rowptr + node);
    int end = __ldg(rowptr + node + 1);
    for (; e + 8 <= end; e += 8) {
        int s0 = __ldg(col + e),     s1 = __ldg(col + e + 1);
        int s2 = __ldg(col + e + 2), s3 = __ldg(col + e + 3);
        int s4 = __ldg(col + e + 4), s5 = __ldg(col + e + 5);
        int s6 = __ldg(col + e + 6), s7 = __ldg(col + e + 7);
        float4 v0 = h2f4(__ldg(hh + (size_t)s0 * 16 + lane));
        float4 v1 = h2f4(__ldg(hh + (size_t)s1 * 16 + lane));
        float4 v2 = h2f4(__ldg(hh + (size_t)s2 * 16 + lane));
        float4 v3 = h2f4(__ldg(hh + (size_t)s3 * 16 + lane));
        float4 v4 = h2f4(__ldg(hh + (size_t)s4 * 16 + lane));
        float4 v5 = h2f4(__ldg(hh + (size_t)s5 * 16 + lane));
        float4 v6 = h2f4(__ldg(hh + (size_t)s6 * 16 + lane));
        float4 v7 = h2f4(__ldg(hh + (size_t)s7 * 16 + lane));
        acc.x += ((v0.x + v1.x) + (v2.x + v3.x)) + ((v4.x + v5.x) + (v6.x + v7.x));
        acc.y += ((v0.y + v1.y) + (v2.y + v3.y)) + ((v4.y + v5.y) + (v6.y + v7.y));
        acc.z += ((v0.z + v1.z) + (v2.z + v3.z)) + ((v4.z + v5.z) + (v6.z + v7.z));
        acc.w += ((v0.w + v1.w) + (v2.w + v3.w)) + ((v4.w + v5.w) + (v6.w + v7.w));
    }
    for (; e + 4 <= end; e += 4) {
        int s0 = __ldg(col + e),     s1 = __ldg(col + e + 1);
        int s2 = __ldg(col + e + 2), s3 = __ldg(col + e + 3);
        float4 v0 = h2f4(__ldg(hh + (size_t)s0 * 16 + lane));
        float4 v1 = h2f4(__ldg(hh + (size_t)s1 * 16 + lane));
        float4 v2 = h2f4(__ldg(hh + (size_t)s2 * 16 + lane));
        float4 v3 = h2f4(__ldg(hh + (size_t)s3 * 16 + lane));
        acc.x += (v0.x + v1.x) + (v2.x + v3.x);
        acc.y += (v0.y + v1.y) + (v2.y + v3.y);
        acc.z += (v0.z + v1.z) + (v2.z + v3.z);
        acc.w += (v0.w + v1.w) + (v2.w + v3.w);
    }
    for (; e < end; e++) {
        int s = __ldg(col + e);
        float4 v = h2f4(__ldg(hh + (size_t)s * 16 + lane));
        acc.x += v.x; acc.y += v.y; acc.z += v.z; acc.w += v.w;
    }
    ((float4*)zout)[(size_t)node * 16 + lane] = acc;
}

// ---------------------------------------------------------------------------
// gemmA: hh = fp16(x @ w1)  (x: [N,128]). 2 nodes/thread, 32 cols each.
// ---------------------------------------------------------------------------
__global__ __launch_bounds__(128) void gemmA_kernel(
    const float* __restrict__ x, const float* __restrict__ w1,
    uint2* __restrict__ hh, int n_nodes)
{
    __shared__ float ws[128 * 64];   // 32KB
    int tid = threadIdx.x;
    for (int i = tid; i < 128 * 64; i += 128) ws[i] = w1[i];
    __syncthreads();

    int half = tid & 1, q = tid >> 1;
    int halfoff = half * 32;
    int n0 = blockIdx.x * 128 + 2 * q, n1 = n0 + 1;
    bool a0 = n0 < n_nodes, a1 = n1 < n_nodes;
    int n0c = a0 ? n0 : n_nodes - 1, n1c = a1 ? n1 : n_nodes - 1;

    ull acc[2][16];
#pragma unroll
    for (int j = 0; j < 16; j++) { acc[0][j] = 0ull; acc[1][j] = 0ull; }

    const float4* r0 = (const float4*)(x + (size_t)n0c * 128);
    const float4* r1 = (const float4*)(x + (size_t)n1c * 128);
#pragma unroll 4
    for (int k4 = 0; k4 < 32; k4++) {
        float4 v0 = __ldg(r0 + k4), v1 = __ldg(r1 + k4);
        float f0[4] = {v0.x, v0.y, v0.z, v0.w};
        float f1[4] = {v1.x, v1.y, v1.z, v1.w};
#pragma unroll
        for (int kk = 0; kk < 4; kk++)
            fma_k32_dual(acc[0], acc[1], ws, k4 * 4 + kk, halfoff, f0[kk], f1[kk]);
    }

    int ubase = halfoff >> 2;
#pragma unroll
    for (int nd = 0; nd < 2; nd++) {
        bool act = nd ? a1 : a0;
        if (!act) continue;
        int n = nd ? n1 : n0;
        uint2* orow = hh + (size_t)n * 16;
#pragma unroll
        for (int qq = 0; qq < 8; qq++) {
            float a, b, c, d;
            unpack2(acc[nd][qq * 2 + 0], a, b);
            unpack2(acc[nd][qq * 2 + 1], c, d);
            orow[ubase + qq] = f4h(a, b, c, d);
        }
    }
}

// ---------------------------------------------------------------------------
// mlpB (layer-1 tail): h = relu( relu(BN(z + b1)) @ w2 + b2 ); fp16 store + pool.
// ---------------------------------------------------------------------------
__global__ __launch_bounds__(128) void mlpB_kernel(
    const float* __restrict__ z,
    const float* __restrict__ b1,
    const float* __restrict__ gg, const float* __restrict__ bt,
    const float* __restrict__ rm, const float* __restrict__ rv,
    const float* __restrict__ w2, const float* __restrict__ b2,
    uint2*       __restrict__ hh,
    const int*   __restrict__ batch,
    float*       __restrict__ pool, int pool_off, int n_nodes)
{
    __shared__ float ws[64 * 64];      // 16KB (w2)
    __shared__ float tile[64 * 128];   // 32KB [col][node]
    int tid = threadIdx.x;
    for (int i = tid; i < 64 * 64; i += 128) ws[i] = w2[i];

    int half = tid & 1, q = tid >> 1;
    int halfoff = half * 32;
    int n0 = blockIdx.x * 128 + 2 * q, n1 = n0 + 1;
    bool a0 = n0 < n_nodes, a1 = n1 < n_nodes;
    int n0c = a0 ? n0 : n_nodes - 1, n1c = a1 ? n1 : n_nodes - 1;

    const float4* zr0 = (const float4*)(z + (size_t)n0c * 64 + halfoff);
    const float4* zr1 = (const float4*)(z + (size_t)n1c * 64 + halfoff);
#pragma unroll
    for (int qq = 0; qq < 8; qq++) {
        float4 v0 = __ldg(zr0 + qq), v1 = __ldg(zr1 + qq);
        ull p00 = pack2(v0.x, v0.y), p01 = pack2(v0.z, v0.w);
        ull p10 = pack2(v1.x, v1.y), p11 = pack2(v1.z, v1.w);
        int j = halfoff + qq * 4;
        bn_pair(p00, p10, j,     b1, gg, bt, rm, rv);
        bn_pair(p01, p11, j + 2, b1, gg, bt, rm, rv);
        float x0, x1, y0, y1;
        unpack2(p00, x0, x1); unpack2(p10, y0, y1);
        *(float2*)&tile[(j + 0) * 128 + 2 * q] = make_float2(x0, y0);
        *(float2*)&tile[(j + 1) * 128 + 2 * q] = make_float2(x1, y1);
        unpack2(p01, x0, x1); unpack2(p11, y0, y1);
        *(float2*)&tile[(j + 2) * 128 + 2 * q] = make_float2(x0, y0);
        *(float2*)&tile[(j + 3) * 128 + 2 * q] = make_float2(x1, y1);
    }
    __syncthreads();

    ull out[2][16];
#pragma unroll
    for (int j = 0; j < 16; j++) { out[0][j] = 0ull; out[1][j] = 0ull; }
#pragma unroll 4
    for (int k = 0; k < 64; k++) {
        float2 hv = *(const float2*)&tile[k * 128 + 2 * q];
        fma_k32_dual(out[0], out[1], ws, k, halfoff, hv.x, hv.y);
    }

    uint2* o0 = hh + (size_t)n0 * 16;
    uint2* o1 = hh + (size_t)n1 * 16;
    float* p0 = a0 ? (pool + (size_t)__ldg(batch + n0) * 192 + pool_off) : pool;
    float* p1 = a1 ? (pool + (size_t)__ldg(batch + n1) * 192 + pool_off) : pool;
    epi_node(out[0], halfoff, b2, o0, p0, a0);
    epi_node(out[1], halfoff, b2, o1, p1, a1);
}

// ---------------------------------------------------------------------------
// mlp64: full fused layer (layers 2/3). 2 nodes/thread, smem tile handoff.
// ---------------------------------------------------------------------------
__global__ __launch_bounds__(128) void mlp64_kernel(
    const float* __restrict__ agg,
    const float* __restrict__ w1, const float* __restrict__ b1,
    const float* __restrict__ gg, const float* __restrict__ bt,
    const float* __restrict__ rm, const float* __restrict__ rv,
    const float* __restrict__ w2, const float* __restrict__ b2,
    uint2*       __restrict__ hh,
    const int*   __restrict__ batch,
    float*       __restrict__ pool, int pool_off, int n_nodes)
{
    __shared__ float ws[64 * 64];      // 16KB (w1 then w2)
    __shared__ float tile[64 * 128];   // 32KB [col][node]
    int tid = threadIdx.x;
    for (int i = tid; i < 64 * 64; i += 128) ws[i] = w1[i];
    __syncthreads();

    int half = tid & 1, q = tid >> 1;
    int halfoff = half * 32;
    int n0 = blockIdx.x * 128 + 2 * q, n1 = n0 + 1;
    bool a0 = n0 < n_nodes, a1 = n1 < n_nodes;
    int n0c = a0 ? n0 : n_nodes - 1, n1c = a1 ? n1 : n_nodes - 1;

    // ---- GEMM1 ----
    ull acc[2][16];
#pragma unroll
    for (int j = 0; j < 16; j++) { acc[0][j] = 0ull; acc[1][j] = 0ull; }

    const float4* r0 = (const float4*)(agg + (size_t)n0c * 64);
    const float4* r1 = (const float4*)(agg + (size_t)n1c * 64);
#pragma unroll 4
    for (int k4 = 0; k4 < 16; k4++) {
        float4 v0 = __ldg(r0 + k4), v1 = __ldg(r1 + k4);
        float f0[4] = {v0.x, v0.y, v0.z, v0.w};
        float f1[4] = {v1.x, v1.y, v1.z, v1.w};
#pragma unroll
        for (int kk = 0; kk < 4; kk++)
            fma_k32_dual(acc[0], acc[1], ws, k4 * 4 + kk, halfoff, f0[kk], f1[kk]);
    }

    // ---- BN + ReLU -> tile ----
#pragma unroll
    for (int j2 = 0; j2 < 16; j2++) {
        int j = halfoff + 2 * j2;
        bn_pair(acc[0][j2], acc[1][j2], j, b1, gg, bt, rm, rv);
        float x0, x1, y0, y1;
        unpack2(acc[0][j2], x0, x1);
        unpack2(acc[1][j2], y0, y1);
        *(float2*)&tile[(j + 0) * 128 + 2 * q] = make_float2(x0, y0);
        *(float2*)&tile[(j + 1) * 128 + 2 * q] = make_float2(x1, y1);
    }

    // ---- swap weights ----
    __syncthreads();
    for (int i = tid; i < 64 * 64; i += 128) ws[i] = w2[i];
    __syncthreads();

    // ---- GEMM2 ----
    ull out[2][16];
#pragma unroll
    for (int j = 0; j < 16; j++) { out[0][j] = 0ull; out[1][j] = 0ull; }
#pragma unroll 4
    for (int k = 0; k < 64; k++) {
        float2 hv = *(const float2*)&tile[k * 128 + 2 * q];
        fma_k32_dual(out[0], out[1], ws, k, halfoff, hv.x, hv.y);
    }

    uint2* o0 = hh + (size_t)n0 * 16;
    uint2* o1 = hh + (size_t)n1 * 16;
    float* p0 = a0 ? (pool + (size_t)__ldg(batch + n0) * 192 + pool_off) : pool;
    float* p1 = a1 ? (pool + (size_t)__ldg(batch + n1) * 192 + pool_off) : pool;
    epi_node(out[0], halfoff, b2, o0, p0, a0);
    epi_node(out[1], halfoff, b2, o1, p1, a1);
}

// ---------------------------------------------------------------------------
__global__ void final_kernel(const float* __restrict__ pool,
                             const float* __restrict__ lw1, const float* __restrict__ lb1,
                             const float* __restrict__ lw2, const float* __restrict__ lb2,
                             float* __restrict__ out)
{
    __shared__ float prow[192];
    __shared__ float hid[64];
    __shared__ float zz[2];
    int g = blockIdx.x, j = threadIdx.x;
    for (int k = j; k < 192; k += 64) prow[k] = pool[g * 192 + k];
    __syncthreads();
    float a = __ldg(lb1 + j);
    for (int k = 0; k < 192; k++) a = fmaf(prow[k], __ldg(lw1 + k * 64 + j), a);
    hid[j] = fmaxf(a, 0.f);
    __syncthreads();
    if (j < 2) {
        float z = __ldg(lb2 + j);
#pragma unroll 8
        for (int k = 0; k < 64; k++) z = fmaf(hid[k], __ldg(lw2 + k * 2 + j), z);
        zz[j] = z;
    }
    __syncthreads();
    if (j == 0) {
        float m   = fmaxf(zz[0], zz[1]);
        float lse = m + logf(expf(zz[0] - m) + expf(zz[1] - m));
        out[g * 2 + 0] = zz[0] - lse;
        out[g * 2 + 1] = zz[1] - lse;
    }
}

// ---------------------------------------------------------------------------
extern "C" void kernel_launch(void* const* d_in, const int* in_sizes, int n_in,
                              void* d_out, int out_size)
{
    const float* x     = (const float*)d_in[0];
    const int*   ei    = (const int*)  d_in[1];
    const int*   batch = (const int*)  d_in[2];

    int wi = (in_sizes[3] < 64) ? 4 : 3;
    const float* W[28];
    for (int i = 0; i < 28 && wi + i < n_in; i++) W[i] = (const float*)d_in[wi + i];

    int n_nodes = in_sizes[0] / 128;
    int n_edges = in_sizes[1] / 2;

    float *z, *pool;
    uint2 *hh;
    int *deg, *row, *cur, *col, *bsum;
    cudaGetSymbolAddress((void**)&z,    g_z);
    cudaGetSymbolAddress((void**)&hh,   g_hh);
    cudaGetSymbolAddress((void**)&pool, g_pool);
    cudaGetSymbolAddress((void**)&deg,  g_deg);
    cudaGetSymbolAddress((void**)&row,  g_row);
    cudaGetSymbolAddress((void**)&cur,  g_cur);
    cudaGetSymbolAddress((void**)&col,  g_col);
    cudaGetSymbolAddress((void**)&bsum, g_bsum);

    float* out = (float*)d_out;

    int mlpBlocks  = (n_nodes + 127) / 128;
    int pullBlocks = (n_nodes * 16 + 255) / 256;
    int scanBlocks = (n_nodes + SCAN_B - 1) / SCAN_B;

    // ---- CSR build ----
    zero_i_kernel<<<(n_nodes + 1 + 255) / 256, 256>>>(deg, n_nodes + 1);
    zero_f_kernel<<<(NGRAPH * 192 + 255) / 256, 256>>>(pool, NGRAPH * 192);
    hist_kernel<<<(n_edges + 255) / 256, 256>>>(ei, deg, n_edges);
    bsum_kernel<<<scanBlocks, SCAN_B>>>(deg, bsum, n_nodes);
    bscan_kernel<<<1, 32>>>(bsum, scanBlocks);
    scatter_scan_kernel<<<scanBlocks, SCAN_B>>>(deg, bsum, row, cur, n_nodes);
    fill_kernel<<<(n_edges + 255) / 256, 256>>>(ei, cur, col, n_edges);

    // ---- layer 1: hh = fp16(x@w11) ; z = pull(hh) ; hh = mlpB(z) ----
    gemmA_kernel<<<mlpBlocks, 128>>>(x, W[0], hh, n_nodes);
    pull64h_kernel<<<pullBlocks, 256>>>(hh, row, col, z, n_nodes);
    mlpB_kernel<<<mlpBlocks, 128>>>(z, W[1], W[2], W[3], W[4], W[5], W[6], W[7],
                                    hh, batch, pool, 0, n_nodes);

    // ---- layer 2 ----
    pull64h_kernel<<<pullBlocks, 256>>>(hh, row, col, z, n_nodes);
    mlp64_kernel<<<mlpBlocks, 128>>>(z, W[8], W[9], W[10], W[11], W[12], W[13], W[14], W[15],
                                     hh, batch, pool, 64, n_nodes);

    // ---- layer 3 ----
    pull64h_kernel<<<pullBlocks, 256>>>(hh, row, col, z, n_nodes);
    mlp64_kernel<<<mlpBlocks, 128>>>(z, W[16], W[17], W[18], W[19], W[20], W[21], W[22], W[23],
                                     hh, batch, pool, 128, n_nodes);

    final_kernel<<<NGRAPH, 64>>>(pool, W[24], W[25], W[26], W[27], out);
}